// round 2
// baseline (speedup 1.0000x reference)
#include <cuda_runtime.h>
#include <cstdint>

#define LQ 64
#define DQ 128
#define EPSQ 1e-6f
#define MAXB 2048

// Precomputed MLP collapse vectors: Vp = relu(W1)^T W2, Vn = min(W1,0)^T W2
__device__ float g_Vp[DQ];
__device__ float g_Vn[DQ];
__device__ int   g_b1_zero;
// Scratch for the (never-taken-in-practice) general-b1 fallback path.
__device__ float g_feats[2u * MAXB * LQ * 8u];

// ---------------------------------------------------------------------------
// Prep: fold W1 through W2 (positive / negative parts), detect b1 == 0.
// ---------------------------------------------------------------------------
__global__ void prep_kernel(const float* __restrict__ W1,
                            const float* __restrict__ b1,
                            const float* __restrict__ W2) {
    int e = threadIdx.x;  // 128 threads
    float vp = 0.f, vn = 0.f;
    #pragma unroll 8
    for (int d = 0; d < DQ; ++d) {
        float w  = W1[d];
        float w2 = W2[d * DQ + e];
        vp = fmaf(fmaxf(w, 0.f), w2, vp);
        vn = fmaf(fminf(w, 0.f), w2, vn);
    }
    g_Vp[e] = vp;
    g_Vn[e] = vn;

    __shared__ int nz;
    if (e == 0) nz = 0;
    __syncthreads();
    if (b1[e] != 0.f) atomicAdd(&nz, 1);
    __syncthreads();
    if (e == 0) g_b1_zero = (nz == 0) ? 1 : 0;
}

// ---------------------------------------------------------------------------
// Main: one block per sample. Threads 0..127 compute per-position features
// (side = tid>>6, pos = tid&63); all 256 threads stream the 64 KB output.
// ---------------------------------------------------------------------------
__global__ __launch_bounds__(256)
void lpe_main_kernel(const int*   __restrict__ src_ids,
                     const int*   __restrict__ dst_ids,
                     const int*   __restrict__ src_nid,
                     const int*   __restrict__ dst_nid,
                     const float* __restrict__ itimes,
                     const float* __restrict__ src_t,
                     const float* __restrict__ dst_t,
                     const float* __restrict__ b2,
                     float*       __restrict__ out,
                     int B) {
    __shared__ int   s_ids[2][LQ];
    __shared__ float s_t[2][LQ];
    __shared__ int   s_rank[2][LQ];
    __shared__ float s_avg[2][LQ];
    __shared__ float s_rec[2][LQ];
    __shared__ float s_Sp[2][LQ];
    __shared__ float s_Sn[2][LQ];
    __shared__ float s_Vp[DQ], s_Vn[DQ], s_b2[DQ];

    const int b   = blockIdx.x;
    const int tid = threadIdx.x;

    // ---- load tile ----
    if (tid < 128) {
        int side = tid >> 6, p = tid & 63;
        const int*   ids = side ? dst_ids : src_ids;
        const float* ts  = side ? dst_t   : src_t;
        s_ids[side][p] = ids[b * LQ + p];
        s_t[side][p]   = ts[b * LQ + p];
    } else {
        int e = tid - 128;
        s_Vp[e] = g_Vp[e];
        s_Vn[e] = g_Vn[e];
        s_b2[e] = b2[e];
    }
    __syncthreads();

    const int fast = g_b1_zero;

    // per-thread state carried across phases (only meaningful for tid<128)
    int   myid = 0, n = 0;
    float myt = 0.f, tmax = 0.f, tmin = 0.f;

    // ---- phase 1: group size / extrema / stable rank (j is warp-uniform -> broadcast LDS) ----
    if (tid < 128) {
        int side = tid >> 6, i = tid & 63;
        myid = s_ids[side][i];
        myt  = s_t[side][i];
        int rank = 0;
        tmax = -3.402823466e38f;
        tmin =  3.402823466e38f;
        #pragma unroll 4
        for (int j = 0; j < LQ; ++j) {
            int   idj = s_ids[side][j];
            float tj  = s_t[side][j];
            if (idj == myid) {
                ++n;
                tmax = fmaxf(tmax, tj);
                tmin = fminf(tmin, tj);
                if (tj < myt || (tj == myt && j < i)) ++rank;
            }
        }
        s_rank[side][i] = rank;
    }
    __syncthreads();

    // ---- phase 2: order statistic t_split -> avg_iat / recent_iat ----
    if (tid < 128) {
        int side = tid >> 6, i = tid & 63;
        int split = n >> 1;
        float tsplit = 0.f;
        #pragma unroll 4
        for (int j = 0; j < LQ; ++j) {
            if (s_ids[side][j] == myid && s_rank[side][j] == split)
                tsplit = s_t[side][j];
        }
        float nf  = (float)n;
        float avg = (n > 1) ? (tmax - tmin) / (nf - 1.f) : 0.f;
        float den = fmaxf(nf - (float)split - 1.f, 1.f);
        float rec = (n >= 4) ? (tmax - tsplit) / den : 0.f;
        if (myid == 0) { avg = 0.f; rec = 0.f; }
        s_avg[side][i] = avg;
        s_rec[side][i] = rec;
    }
    __syncthreads();

    // ---- phase 3: cross-side lookups + 8 features -> signed sums ----
    if (tid < 128) {
        int side = tid >> 6, i = tid & 63;
        int os = side ^ 1;
        float cur_t      = itimes[b];
        int   other_node = side ? src_nid[b] : dst_nid[b];

        int   c_other = 0, found = 0;
        float lt = 0.f, iat_o = 0.f, riat_o = 0.f;
        #pragma unroll 4
        for (int j = 0; j < LQ; ++j) {
            int bj = s_ids[os][j];
            if (bj == myid) {
                ++c_other;                 // raw count (id 0 included, masked below)
                if (bj != 0) {
                    lt = s_t[os][j];       // last occurrence wins
                    if (!found) {          // first occurrence wins
                        iat_o  = s_avg[os][j];
                        riat_o = s_rec[os][j];
                        found = 1;
                    }
                }
            }
        }

        float f0 = (float)n;                                   // c_self
        float f1 = (float)c_other;                             // c_other
        float f2 = (myid == other_node) ? 1.f : 0.f;           // is_other
        float f3 = (c_other > 0) ? 1.f : 0.f;                  // connects
        float f4 = (c_other > 0) ? f0 / (f1 + EPSQ) : 0.f;     // freq_asym
        float rcy_self  = cur_t - myt;
        float rcy_other = cur_t - lt;
        float f5 = (rcy_self > EPSQ) ? rcy_other / (rcy_self + EPSQ) : 0.f;
        float my_avg = s_avg[side][i], my_rec = s_rec[side][i];
        float f6 = (iat_o  > EPSQ) ? my_avg / (iat_o  + EPSQ) : 0.f;
        float f7 = (riat_o > EPSQ) ? my_rec / (riat_o + EPSQ) : 0.f;
        if (myid == 0) { f0 = f1 = f2 = f3 = f4 = f5 = f6 = f7 = 0.f; }

        float sp = fmaxf(f0,0.f)+fmaxf(f1,0.f)+fmaxf(f2,0.f)+fmaxf(f3,0.f)
                 + fmaxf(f4,0.f)+fmaxf(f5,0.f)+fmaxf(f6,0.f)+fmaxf(f7,0.f);
        float sn = fminf(f0,0.f)+fminf(f1,0.f)+fminf(f2,0.f)+fminf(f3,0.f)
                 + fminf(f4,0.f)+fminf(f5,0.f)+fminf(f6,0.f)+fminf(f7,0.f);
        s_Sp[side][i] = sp;
        s_Sn[side][i] = sn;

        if (!fast && b < MAXB) {           // stash feats for general fallback
            float* fp = &g_feats[(((size_t)side * B + b) * LQ + i) * 8];
            fp[0]=f0; fp[1]=f1; fp[2]=f2; fp[3]=f3;
            fp[4]=f4; fp[5]=f5; fp[6]=f6; fp[7]=f7;
        }
    }
    __syncthreads();

    // ---- phase 4: fast-path output, y = Sp*Vp + Sn*Vn + 8*b2, float4 streamed ----
    if (fast) {
        const float4* Vp4 = (const float4*)s_Vp;
        const float4* Vn4 = (const float4*)s_Vn;
        const float4* B24 = (const float4*)s_b2;
        const size_t sideStride = (size_t)B * (LQ * DQ);
        const size_t base       = (size_t)b * (LQ * DQ);
        #pragma unroll 4
        for (int w = tid; w < 2 * LQ * (DQ / 4); w += 256) {
            int e4   = w & 31;
            int l    = (w >> 5) & 63;
            int side = w >> 11;
            float sp = s_Sp[side][l], sn = s_Sn[side][l];
            float4 vp = Vp4[e4], vn = Vn4[e4], bb = B24[e4];
            float4 y;
            y.x = fmaf(sp, vp.x, fmaf(sn, vn.x, 8.f * bb.x));
            y.y = fmaf(sp, vp.y, fmaf(sn, vn.y, 8.f * bb.y));
            y.z = fmaf(sp, vp.z, fmaf(sn, vn.z, 8.f * bb.z));
            y.w = fmaf(sp, vp.w, fmaf(sn, vn.w, 8.f * bb.w));
            float4* row = (float4*)(out + side * sideStride + base + (size_t)l * DQ);
            row[e4] = y;
        }
    }
}

// ---------------------------------------------------------------------------
// General-b1 fallback (early-exits when b1 == 0, i.e. always in this dataset).
// ---------------------------------------------------------------------------
__global__ __launch_bounds__(256)
void lpe_fallback_kernel(const float* __restrict__ W1,
                         const float* __restrict__ b1,
                         const float* __restrict__ W2,
                         const float* __restrict__ b2,
                         float*       __restrict__ out,
                         int B) {
    if (g_b1_zero) return;
    __shared__ float sW1[DQ], sb1[DQ];
    int tid = threadIdx.x;
    if (tid < DQ) { sW1[tid] = W1[tid]; sb1[tid] = b1[tid]; }
    __syncthreads();
    int b = blockIdx.x;
    if (b >= MAXB) return;
    for (int w = tid; w < 2 * LQ * DQ / 1; w += 256) {
        // w enumerates (side, l, e) as row*128 + e with row = side*64 + l
        int e    = w & 127;
        int row  = w >> 7;
        int side = row >> 6, l = row & 63;
        if (row >= 128) break;
        const float* fp = &g_feats[(((size_t)side * B + b) * LQ + l) * 8];
        float y = 8.f * b2[e];
        #pragma unroll
        for (int f = 0; f < 8; ++f) {
            float fv  = fp[f];
            float acc = 0.f;
            for (int d = 0; d < DQ; ++d) {
                float h = fmaxf(fmaf(fv, sW1[d], sb1[d]), 0.f);
                acc = fmaf(h, __ldg(&W2[d * DQ + e]), acc);
            }
            y += acc;
        }
        out[((size_t)side * B + b) * (LQ * DQ) + (size_t)l * DQ + e] = y;
    }
}

// ---------------------------------------------------------------------------
extern "C" void kernel_launch(void* const* d_in, const int* in_sizes, int n_in,
                              void* d_out, int out_size) {
    const int*   src_ids = (const int*)  d_in[0];
    const int*   dst_ids = (const int*)  d_in[1];
    const int*   src_nid = (const int*)  d_in[2];
    const int*   dst_nid = (const int*)  d_in[3];
    const float* itimes  = (const float*)d_in[4];
    const float* src_t   = (const float*)d_in[5];
    const float* dst_t   = (const float*)d_in[6];
    const float* W1      = (const float*)d_in[7];
    const float* b1      = (const float*)d_in[8];
    const float* W2      = (const float*)d_in[9];
    const float* b2      = (const float*)d_in[10];
    float* out = (float*)d_out;
    int B = in_sizes[2];  // src_node_ids count

    prep_kernel<<<1, 128>>>(W1, b1, W2);
    lpe_main_kernel<<<B, 256>>>(src_ids, dst_ids, src_nid, dst_nid,
                                itimes, src_t, dst_t, b2, out, B);
    lpe_fallback_kernel<<<B, 256>>>(W1, b1, W2, b2, out, B);
}

// round 3
// speedup vs baseline: 1.1909x; 1.1909x over previous
#include <cuda_runtime.h>
#include <cstdint>

#define LQ 64
#define DQ 128
#define EPSQ 1e-6f

// Precomputed MLP collapse vectors: Vp = relu(W1)^T W2, Vn = min(W1,0)^T W2
__device__ float g_Vp[DQ];
__device__ float g_Vn[DQ];
__device__ int   g_b1_zero;

// ---------------------------------------------------------------------------
// Prep: fold W1 through W2 (positive/negative parts), detect b1 == 0.
// 1024 threads: thread t handles e = t&127, d-chunk dg = t>>7 (16 d's each).
// Loads of W2[d*128+e] are fully coalesced (consecutive t -> consecutive e).
// ---------------------------------------------------------------------------
__global__ __launch_bounds__(1024)
void prep_kernel(const float* __restrict__ W1,
                 const float* __restrict__ b1,
                 const float* __restrict__ W2) {
    __shared__ float rvp[8][DQ];
    __shared__ float rvn[8][DQ];
    __shared__ int nz;
    const int t  = threadIdx.x;
    const int e  = t & 127;
    const int dg = t >> 7;

    float vp = 0.f, vn = 0.f;
    #pragma unroll
    for (int k = 0; k < 16; ++k) {
        int d = dg * 16 + k;
        float w  = __ldg(&W1[d]);
        float w2 = __ldg(&W2[d * DQ + e]);
        vp = fmaf(fmaxf(w, 0.f), w2, vp);
        vn = fmaf(fminf(w, 0.f), w2, vn);
    }
    rvp[dg][e] = vp;
    rvn[dg][e] = vn;

    if (t == 0) nz = 0;
    __syncthreads();
    if (t < DQ && b1[t] != 0.f) atomicAdd(&nz, 1);
    __syncthreads();

    if (t < DQ) {
        float sp = 0.f, sn = 0.f;
        #pragma unroll
        for (int g = 0; g < 8; ++g) { sp += rvp[g][t]; sn += rvn[g][t]; }
        g_Vp[t] = sp;
        g_Vn[t] = sn;
    }
    if (t == 0) g_b1_zero = (nz == 0) ? 1 : 0;
}

// ---------------------------------------------------------------------------
// Main: one block per sample. Threads 0..127 compute per-position features
// (side = tid>>6, pos = tid&63); all 256 threads stream the 64 KB output.
// General-b1 MLP path is inlined (taken only if b1 != 0; never in dataset).
// ---------------------------------------------------------------------------
__global__ __launch_bounds__(256)
void lpe_main_kernel(const int*   __restrict__ src_ids,
                     const int*   __restrict__ dst_ids,
                     const int*   __restrict__ src_nid,
                     const int*   __restrict__ dst_nid,
                     const float* __restrict__ itimes,
                     const float* __restrict__ src_t,
                     const float* __restrict__ dst_t,
                     const float* __restrict__ W1,
                     const float* __restrict__ b1,
                     const float* __restrict__ W2,
                     const float* __restrict__ b2,
                     float*       __restrict__ out,
                     int B) {
    __shared__ int   s_ids[2][LQ];
    __shared__ float s_t[2][LQ];
    __shared__ int   s_rank[2][LQ];
    __shared__ float s_avg[2][LQ];
    __shared__ float s_rec[2][LQ];
    __shared__ float s_Sp[2][LQ];
    __shared__ float s_Sn[2][LQ];
    __shared__ float s_Vp[DQ], s_Vn[DQ], s_b2[DQ];
    __shared__ float s_feat[2][LQ][8];   // only written on the slow path

    const int b   = blockIdx.x;
    const int tid = threadIdx.x;

    // ---- load tile ----
    if (tid < 128) {
        int side = tid >> 6, p = tid & 63;
        const int*   ids = side ? dst_ids : src_ids;
        const float* ts  = side ? dst_t   : src_t;
        s_ids[side][p] = ids[b * LQ + p];
        s_t[side][p]   = ts[b * LQ + p];
    } else {
        int e = tid - 128;
        s_Vp[e] = g_Vp[e];
        s_Vn[e] = g_Vn[e];
        s_b2[e] = b2[e];
    }
    __syncthreads();

    const int fast = g_b1_zero;

    int   myid = 0, n = 0;
    float myt = 0.f, tmax = 0.f, tmin = 0.f;

    // ---- phase 1: group size / extrema / stable rank ----
    if (tid < 128) {
        int side = tid >> 6, i = tid & 63;
        myid = s_ids[side][i];
        myt  = s_t[side][i];
        int rank = 0;
        tmax = -3.402823466e38f;
        tmin =  3.402823466e38f;
        #pragma unroll 4
        for (int j = 0; j < LQ; ++j) {
            int   idj = s_ids[side][j];
            float tj  = s_t[side][j];
            if (idj == myid) {
                ++n;
                tmax = fmaxf(tmax, tj);
                tmin = fminf(tmin, tj);
                if (tj < myt || (tj == myt && j < i)) ++rank;
            }
        }
        s_rank[side][i] = rank;
    }
    __syncthreads();

    // ---- phase 2: order statistic t_split -> avg_iat / recent_iat ----
    if (tid < 128) {
        int side = tid >> 6, i = tid & 63;
        int split = n >> 1;
        float tsplit = 0.f;
        #pragma unroll 4
        for (int j = 0; j < LQ; ++j) {
            if (s_ids[side][j] == myid && s_rank[side][j] == split)
                tsplit = s_t[side][j];
        }
        float nf  = (float)n;
        float avg = (n > 1) ? (tmax - tmin) / (nf - 1.f) : 0.f;
        float den = fmaxf(nf - (float)split - 1.f, 1.f);
        float rec = (n >= 4) ? (tmax - tsplit) / den : 0.f;
        if (myid == 0) { avg = 0.f; rec = 0.f; }
        s_avg[side][i] = avg;
        s_rec[side][i] = rec;
    }
    __syncthreads();

    // ---- phase 3: cross-side lookups + 8 features -> signed sums ----
    if (tid < 128) {
        int side = tid >> 6, i = tid & 63;
        int os = side ^ 1;
        float cur_t      = itimes[b];
        int   other_node = side ? src_nid[b] : dst_nid[b];

        int   c_other = 0, found = 0;
        float lt = 0.f, iat_o = 0.f, riat_o = 0.f;
        #pragma unroll 4
        for (int j = 0; j < LQ; ++j) {
            int bj = s_ids[os][j];
            if (bj == myid) {
                ++c_other;                 // raw count (id 0 included, masked below)
                if (bj != 0) {
                    lt = s_t[os][j];       // last occurrence wins
                    if (!found) {          // first occurrence wins
                        iat_o  = s_avg[os][j];
                        riat_o = s_rec[os][j];
                        found = 1;
                    }
                }
            }
        }

        float f0 = (float)n;
        float f1 = (float)c_other;
        float f2 = (myid == other_node) ? 1.f : 0.f;
        float f3 = (c_other > 0) ? 1.f : 0.f;
        float f4 = (c_other > 0) ? f0 / (f1 + EPSQ) : 0.f;
        float rcy_self  = cur_t - myt;
        float rcy_other = cur_t - lt;
        float f5 = (rcy_self > EPSQ) ? rcy_other / (rcy_self + EPSQ) : 0.f;
        float my_avg = s_avg[side][i], my_rec = s_rec[side][i];
        float f6 = (iat_o  > EPSQ) ? my_avg / (iat_o  + EPSQ) : 0.f;
        float f7 = (riat_o > EPSQ) ? my_rec / (riat_o + EPSQ) : 0.f;
        if (myid == 0) { f0 = f1 = f2 = f3 = f4 = f5 = f6 = f7 = 0.f; }

        float sp = fmaxf(f0,0.f)+fmaxf(f1,0.f)+fmaxf(f2,0.f)+fmaxf(f3,0.f)
                 + fmaxf(f4,0.f)+fmaxf(f5,0.f)+fmaxf(f6,0.f)+fmaxf(f7,0.f);
        float sn = fminf(f0,0.f)+fminf(f1,0.f)+fminf(f2,0.f)+fminf(f3,0.f)
                 + fminf(f4,0.f)+fminf(f5,0.f)+fminf(f6,0.f)+fminf(f7,0.f);
        s_Sp[side][i] = sp;
        s_Sn[side][i] = sn;

        if (!fast) {
            float* fp = &s_feat[side][i][0];
            fp[0]=f0; fp[1]=f1; fp[2]=f2; fp[3]=f3;
            fp[4]=f4; fp[5]=f5; fp[6]=f6; fp[7]=f7;
        }
    }
    __syncthreads();

    if (fast) {
        // ---- fast path: y = Sp*Vp + Sn*Vn + 8*b2, float4 streamed ----
        const int e4 = tid & 31;                 // loop-invariant per thread
        float4 vp = ((const float4*)s_Vp)[e4];
        float4 vn = ((const float4*)s_Vn)[e4];
        float4 bb = ((const float4*)s_b2)[e4];
        bb.x *= 8.f; bb.y *= 8.f; bb.z *= 8.f; bb.w *= 8.f;

        const size_t sideStride = (size_t)B * (LQ * DQ);
        float* base0 = out + (size_t)b * (LQ * DQ);
        #pragma unroll
        for (int k = 0; k < 16; ++k) {
            int w    = tid + k * 256;
            int l    = (w >> 5) & 63;
            int side = w >> 11;
            float sp = s_Sp[side][l], sn = s_Sn[side][l];
            float4 y;
            y.x = fmaf(sp, vp.x, fmaf(sn, vn.x, bb.x));
            y.y = fmaf(sp, vp.y, fmaf(sn, vn.y, bb.y));
            y.z = fmaf(sp, vp.z, fmaf(sn, vn.z, bb.z));
            y.w = fmaf(sp, vp.w, fmaf(sn, vn.w, bb.w));
            float4* row = (float4*)(base0 + (size_t)side * sideStride + (size_t)l * DQ);
            __stcs(&row[e4], y);                 // streaming store (never re-read)
        }
    } else {
        // ---- general-b1 path (never taken with this dataset's b1 == 0) ----
        __shared__ float sW1[DQ], sb1[DQ];
        if (tid < DQ) { sW1[tid] = W1[tid]; sb1[tid] = b1[tid]; }
        __syncthreads();
        const size_t sideStride = (size_t)B * (LQ * DQ);
        for (int w = tid; w < 2 * LQ * DQ; w += 256) {
            int e    = w & 127;
            int row  = w >> 7;
            int side = row >> 6, l = row & 63;
            float y = 8.f * s_b2[e];
            #pragma unroll
            for (int f = 0; f < 8; ++f) {
                float fv  = s_feat[side][l][f];
                float acc = 0.f;
                for (int d = 0; d < DQ; ++d) {
                    float h = fmaxf(fmaf(fv, sW1[d], sb1[d]), 0.f);
                    acc = fmaf(h, __ldg(&W2[d * DQ + e]), acc);
                }
                y += acc;
            }
            out[(size_t)side * sideStride + (size_t)b * (LQ * DQ) + (size_t)l * DQ + e] = y;
        }
    }
}

// ---------------------------------------------------------------------------
extern "C" void kernel_launch(void* const* d_in, const int* in_sizes, int n_in,
                              void* d_out, int out_size) {
    const int*   src_ids = (const int*)  d_in[0];
    const int*   dst_ids = (const int*)  d_in[1];
    const int*   src_nid = (const int*)  d_in[2];
    const int*   dst_nid = (const int*)  d_in[3];
    const float* itimes  = (const float*)d_in[4];
    const float* src_t   = (const float*)d_in[5];
    const float* dst_t   = (const float*)d_in[6];
    const float* W1      = (const float*)d_in[7];
    const float* b1      = (const float*)d_in[8];
    const float* W2      = (const float*)d_in[9];
    const float* b2      = (const float*)d_in[10];
    float* out = (float*)d_out;
    int B = in_sizes[2];  // src_node_ids count

    prep_kernel<<<1, 1024>>>(W1, b1, W2);
    lpe_main_kernel<<<B, 256>>>(src_ids, dst_ids, src_nid, dst_nid,
                                itimes, src_t, dst_t,
                                W1, b1, W2, b2, out, B);
}

// round 4
// speedup vs baseline: 1.4354x; 1.2053x over previous
#include <cuda_runtime.h>
#include <cstdint>

#define LQ 64
#define DQ 128
#define EPSQ 1e-6f

// Precomputed MLP collapse vectors: Vp = relu(W1)^T W2, Vn = min(W1,0)^T W2
__device__ float g_Vp[DQ];
__device__ float g_Vn[DQ];
__device__ int   g_b1_zero;

// ---------------------------------------------------------------------------
// Prep: fold W1 through W2 (positive/negative parts), detect b1 == 0.
// ---------------------------------------------------------------------------
__global__ __launch_bounds__(1024)
void prep_kernel(const float* __restrict__ W1,
                 const float* __restrict__ b1,
                 const float* __restrict__ W2) {
    __shared__ float rvp[8][DQ];
    __shared__ float rvn[8][DQ];
    __shared__ int nz;
    const int t  = threadIdx.x;
    const int e  = t & 127;
    const int dg = t >> 7;

    float vp = 0.f, vn = 0.f;
    #pragma unroll
    for (int k = 0; k < 16; ++k) {
        int d = dg * 16 + k;
        float w  = __ldg(&W1[d]);
        float w2 = __ldg(&W2[d * DQ + e]);
        vp = fmaf(fmaxf(w, 0.f), w2, vp);
        vn = fmaf(fminf(w, 0.f), w2, vn);
    }
    rvp[dg][e] = vp;
    rvn[dg][e] = vn;

    if (t == 0) nz = 0;
    __syncthreads();
    if (t < DQ && b1[t] != 0.f) atomicAdd(&nz, 1);
    __syncthreads();

    if (t < DQ) {
        float sp = 0.f, sn = 0.f;
        #pragma unroll
        for (int g = 0; g < 8; ++g) { sp += rvp[g][t]; sn += rvn[g][t]; }
        g_Vp[t] = sp;
        g_Vn[t] = sn;
    }
    if (t == 0) g_b1_zero = (nz == 0) ? 1 : 0;
}

// ---------------------------------------------------------------------------
// Main: one block per sample. ALL 256 threads participate in the scans:
// thread -> (pos = tid>>1, half = tid&1); lane pairs combine via shfl_xor(1).
// Cross-side lookups reduced to index tracking + O(1) post-scan fetches.
// ---------------------------------------------------------------------------
__global__ __launch_bounds__(256)
void lpe_main_kernel(const int*   __restrict__ src_ids,
                     const int*   __restrict__ dst_ids,
                     const int*   __restrict__ src_nid,
                     const int*   __restrict__ dst_nid,
                     const float* __restrict__ itimes,
                     const float* __restrict__ src_t,
                     const float* __restrict__ dst_t,
                     const float* __restrict__ W1,
                     const float* __restrict__ b1,
                     const float* __restrict__ W2,
                     const float* __restrict__ b2,
                     float*       __restrict__ out,
                     int B) {
    __shared__ int   s_ids[2][LQ];
    __shared__ float s_t[2][LQ];
    __shared__ int   s_rank[2][LQ];
    __shared__ float s_avg[2][LQ];
    __shared__ float s_rec[2][LQ];
    __shared__ float s_Sp[2][LQ];
    __shared__ float s_Sn[2][LQ];
    __shared__ float s_Vp[DQ], s_Vn[DQ], s_b2[DQ];
    __shared__ float s_feat[2][LQ][8];   // slow path only

    const int b   = blockIdx.x;
    const int tid = threadIdx.x;

    // ---- load tile ----
    if (tid < 128) {
        int sd = tid >> 6, p = tid & 63;
        const int*   ids = sd ? dst_ids : src_ids;
        const float* ts  = sd ? dst_t   : src_t;
        s_ids[sd][p] = ids[b * LQ + p];
        s_t[sd][p]   = ts[b * LQ + p];
    } else {
        int e = tid - 128;
        s_Vp[e] = g_Vp[e];
        s_Vn[e] = g_Vn[e];
        s_b2[e] = b2[e];
    }
    __syncthreads();

    const int fast = g_b1_zero;

    const int half = tid & 1;
    const int pos  = tid >> 1;     // 0..127
    const int side = pos >> 6;
    const int i    = pos & 63;
    const int os   = side ^ 1;
    const int jb   = half << 5;    // 0 or 32

    const int   myid = s_ids[side][i];
    const float myt  = s_t[side][i];

    // ---- fused scan: own-side stats + other-side match indices (32 iters) ----
    int   n = 0, rank = 0, co = 0, jfirst = 127, jlast = -1;
    float tmax = -3.402823466e38f, tmin = 3.402823466e38f;
    #pragma unroll 8
    for (int k = 0; k < 32; ++k) {
        int j = jb + k;
        int   idj = s_ids[side][j];
        float tj  = s_t[side][j];
        if (idj == myid) {
            ++n;
            tmax = fmaxf(tmax, tj);
            tmin = fminf(tmin, tj);
            if (tj < myt || (tj == myt && j < i)) ++rank;
        }
        if (s_ids[os][j] == myid) {
            ++co;
            jfirst = min(jfirst, j);
            jlast  = max(jlast, j);
        }
    }
    n      += __shfl_xor_sync(0xFFFFFFFFu, n, 1);
    rank   += __shfl_xor_sync(0xFFFFFFFFu, rank, 1);
    co     += __shfl_xor_sync(0xFFFFFFFFu, co, 1);
    tmax    = fmaxf(tmax, __shfl_xor_sync(0xFFFFFFFFu, tmax, 1));
    tmin    = fminf(tmin, __shfl_xor_sync(0xFFFFFFFFu, tmin, 1));
    jfirst  = min(jfirst, __shfl_xor_sync(0xFFFFFFFFu, jfirst, 1));
    jlast   = max(jlast,  __shfl_xor_sync(0xFFFFFFFFu, jlast, 1));
    if (!half) s_rank[side][i] = rank;
    __syncthreads();

    // ---- order statistic scan (32 iters) -> avg_iat / recent_iat ----
    const int split = n >> 1;
    float ts = 0.f;
    #pragma unroll 8
    for (int k = 0; k < 32; ++k) {
        int j = jb + k;
        if (s_ids[side][j] == myid && s_rank[side][j] == split)
            ts = s_t[side][j];
    }
    ts += __shfl_xor_sync(0xFFFFFFFFu, ts, 1);   // exactly one match in group

    {
        float nf  = (float)n;
        float avg = (n > 1) ? (tmax - tmin) / (nf - 1.f) : 0.f;
        float den = fmaxf(nf - (float)split - 1.f, 1.f);
        float rec = (n >= 4) ? (tmax - ts) / den : 0.f;
        if (myid == 0) { avg = 0.f; rec = 0.f; }
        if (!half) { s_avg[side][i] = avg; s_rec[side][i] = rec; }
    }
    __syncthreads();

    // ---- features from O(1) lookups ----
    if (!half) {
        float cur_t      = itimes[b];
        int   other_node = side ? src_nid[b] : dst_nid[b];

        float lt     = (jlast  >= 0) ? s_t[os][jlast]    : 0.f;
        float iat_o  = (jfirst < 64) ? s_avg[os][jfirst] : 0.f;
        float riat_o = (jfirst < 64) ? s_rec[os][jfirst] : 0.f;
        float my_avg = s_avg[side][i], my_rec = s_rec[side][i];

        float f0 = (float)n;
        float f1 = (float)co;
        float f2 = (myid == other_node) ? 1.f : 0.f;
        float f3 = (co > 0) ? 1.f : 0.f;
        float f4 = (co > 0) ? f0 / (f1 + EPSQ) : 0.f;
        float rcy_self  = cur_t - myt;
        float rcy_other = cur_t - lt;
        float f5 = (rcy_self > EPSQ) ? rcy_other / (rcy_self + EPSQ) : 0.f;
        float f6 = (iat_o  > EPSQ) ? my_avg / (iat_o  + EPSQ) : 0.f;
        float f7 = (riat_o > EPSQ) ? my_rec / (riat_o + EPSQ) : 0.f;
        if (myid == 0) { f0 = f1 = f2 = f3 = f4 = f5 = f6 = f7 = 0.f; }

        float sp = fmaxf(f0,0.f)+fmaxf(f1,0.f)+fmaxf(f2,0.f)+fmaxf(f3,0.f)
                 + fmaxf(f4,0.f)+fmaxf(f5,0.f)+fmaxf(f6,0.f)+fmaxf(f7,0.f);
        float sn = fminf(f0,0.f)+fminf(f1,0.f)+fminf(f2,0.f)+fminf(f3,0.f)
                 + fminf(f4,0.f)+fminf(f5,0.f)+fminf(f6,0.f)+fminf(f7,0.f);
        s_Sp[side][i] = sp;
        s_Sn[side][i] = sn;

        if (!fast) {
            float* fp = &s_feat[side][i][0];
            fp[0]=f0; fp[1]=f1; fp[2]=f2; fp[3]=f3;
            fp[4]=f4; fp[5]=f5; fp[6]=f6; fp[7]=f7;
        }
    }
    __syncthreads();

    if (fast) {
        // ---- fast path: y = Sp*Vp + Sn*Vn + 8*b2, float4 streamed ----
        const int e4 = tid & 31;                 // loop-invariant per thread
        float4 vp = ((const float4*)s_Vp)[e4];
        float4 vn = ((const float4*)s_Vn)[e4];
        float4 bb = ((const float4*)s_b2)[e4];
        bb.x *= 8.f; bb.y *= 8.f; bb.z *= 8.f; bb.w *= 8.f;

        const size_t sideStride = (size_t)B * (LQ * DQ);
        float* base0 = out + (size_t)b * (LQ * DQ);
        #pragma unroll
        for (int k = 0; k < 16; ++k) {
            int w    = tid + k * 256;
            int l    = (w >> 5) & 63;
            int sd   = w >> 11;
            float sp = s_Sp[sd][l], sn = s_Sn[sd][l];
            float4 y;
            y.x = fmaf(sp, vp.x, fmaf(sn, vn.x, bb.x));
            y.y = fmaf(sp, vp.y, fmaf(sn, vn.y, bb.y));
            y.z = fmaf(sp, vp.z, fmaf(sn, vn.z, bb.z));
            y.w = fmaf(sp, vp.w, fmaf(sn, vn.w, bb.w));
            float4* row = (float4*)(base0 + (size_t)sd * sideStride + (size_t)l * DQ);
            __stcs(&row[e4], y);
        }
    } else {
        // ---- general-b1 path (never taken with this dataset's b1 == 0) ----
        __shared__ float sW1[DQ], sb1[DQ];
        if (tid < DQ) { sW1[tid] = W1[tid]; sb1[tid] = b1[tid]; }
        __syncthreads();
        const size_t sideStride = (size_t)B * (LQ * DQ);
        for (int w = tid; w < 2 * LQ * DQ; w += 256) {
            int e    = w & 127;
            int row  = w >> 7;
            int sd   = row >> 6, l = row & 63;
            float y = 8.f * s_b2[e];
            #pragma unroll
            for (int f = 0; f < 8; ++f) {
                float fv  = s_feat[sd][l][f];
                float acc = 0.f;
                for (int d = 0; d < DQ; ++d) {
                    float h = fmaxf(fmaf(fv, sW1[d], sb1[d]), 0.f);
                    acc = fmaf(h, __ldg(&W2[d * DQ + e]), acc);
                }
                y += acc;
            }
            out[(size_t)sd * sideStride + (size_t)b * (LQ * DQ) + (size_t)l * DQ + e] = y;
        }
    }
}

// ---------------------------------------------------------------------------
extern "C" void kernel_launch(void* const* d_in, const int* in_sizes, int n_in,
                              void* d_out, int out_size) {
    const int*   src_ids = (const int*)  d_in[0];
    const int*   dst_ids = (const int*)  d_in[1];
    const int*   src_nid = (const int*)  d_in[2];
    const int*   dst_nid = (const int*)  d_in[3];
    const float* itimes  = (const float*)d_in[4];
    const float* src_t   = (const float*)d_in[5];
    const float* dst_t   = (const float*)d_in[6];
    const float* W1      = (const float*)d_in[7];
    const float* b1      = (const float*)d_in[8];
    const float* W2      = (const float*)d_in[9];
    const float* b2      = (const float*)d_in[10];
    float* out = (float*)d_out;
    int B = in_sizes[2];  // src_node_ids count

    prep_kernel<<<1, 1024>>>(W1, b1, W2);
    lpe_main_kernel<<<B, 256>>>(src_ids, dst_ids, src_nid, dst_nid,
                                itimes, src_t, dst_t,
                                W1, b1, W2, b2, out, B);
}

// round 5
// speedup vs baseline: 1.8939x; 1.3194x over previous
#include <cuda_runtime.h>
#include <cstdint>

#define LQ 64
#define DQ 128
#define EPSQ 1e-6f

// Precomputed: Vp = relu(W1)^T W2, Vn = min(W1,0)^T W2, Vb = 8*b2
__device__ float g_Vp[DQ];
__device__ float g_Vn[DQ];
__device__ float g_Vb[DQ];
__device__ int   g_b1_zero;

// ---------------------------------------------------------------------------
__global__ __launch_bounds__(1024)
void prep_kernel(const float* __restrict__ W1,
                 const float* __restrict__ b1,
                 const float* __restrict__ W2,
                 const float* __restrict__ b2) {
    __shared__ float rvp[8][DQ];
    __shared__ float rvn[8][DQ];
    __shared__ int nz;
    const int t  = threadIdx.x;
    const int e  = t & 127;
    const int dg = t >> 7;

    float vp = 0.f, vn = 0.f;
    #pragma unroll
    for (int k = 0; k < 16; ++k) {
        int d = dg * 16 + k;
        float w  = __ldg(&W1[d]);
        float w2 = __ldg(&W2[d * DQ + e]);
        vp = fmaf(fmaxf(w, 0.f), w2, vp);
        vn = fmaf(fminf(w, 0.f), w2, vn);
    }
    rvp[dg][e] = vp;
    rvn[dg][e] = vn;

    if (t == 0) nz = 0;
    __syncthreads();
    if (t < DQ && b1[t] != 0.f) atomicAdd(&nz, 1);
    __syncthreads();

    if (t < DQ) {
        float sp = 0.f, sn = 0.f;
        #pragma unroll
        for (int g = 0; g < 8; ++g) { sp += rvp[g][t]; sn += rvn[g][t]; }
        g_Vp[t] = sp;
        g_Vn[t] = sn;
        g_Vb[t] = 8.f * b2[t];
    }
    if (t == 0) g_b1_zero = (nz == 0) ? 1 : 0;
}

// ---------------------------------------------------------------------------
// Main: one block per sample. Lane pairs share a position: half h scans
// j = 2k+h (conflict-free LDS), builds 64-bit membership masks, merged via
// one 64-bit shfl_xor. All group stats then run sparsely over set bits
// (expected group size ~1.1). Cross-side lookups are O(1) via ffs/clz.
// ---------------------------------------------------------------------------
__global__ __launch_bounds__(256)
void lpe_main_kernel(const int*   __restrict__ src_ids,
                     const int*   __restrict__ dst_ids,
                     const int*   __restrict__ src_nid,
                     const int*   __restrict__ dst_nid,
                     const float* __restrict__ itimes,
                     const float* __restrict__ src_t,
                     const float* __restrict__ dst_t,
                     const float* __restrict__ W1,
                     const float* __restrict__ b1,
                     const float* __restrict__ W2,
                     const float* __restrict__ b2,
                     float*       __restrict__ out,
                     int B) {
    __shared__ int   s_ids[2][LQ];
    __shared__ float s_t[2][LQ];
    __shared__ float s_avg[2][LQ];
    __shared__ float s_rec[2][LQ];
    __shared__ float s_Sp[2][LQ];
    __shared__ float s_Sn[2][LQ];
    __shared__ float s_Vp[DQ], s_Vn[DQ], s_Vb[DQ];
    __shared__ float s_feat[2][LQ][8];   // slow path only

    const int b   = blockIdx.x;
    const int tid = threadIdx.x;

    // ---- load tile ----
    if (tid < 128) {
        int sd = tid >> 6, p = tid & 63;
        const int*   ids = sd ? dst_ids : src_ids;
        const float* ts  = sd ? dst_t   : src_t;
        s_ids[sd][p] = ids[b * LQ + p];
        s_t[sd][p]   = ts[b * LQ + p];
    } else {
        int e = tid - 128;
        s_Vp[e] = g_Vp[e];
        s_Vn[e] = g_Vn[e];
        s_Vb[e] = g_Vb[e];
    }
    __syncthreads();

    const int fast = g_b1_zero;

    const int half = tid & 1;
    const int pos  = tid >> 1;     // 0..127
    const int side = pos >> 6;     // warp-uniform
    const int i    = pos & 63;
    const int os   = side ^ 1;

    const int   myid = s_ids[side][i];
    const float myt  = s_t[side][i];

    // ---- mask build: j = 2k + half, constant shifts, <<half at the end ----
    unsigned loA = 0, hiA = 0, loX = 0, hiX = 0;
    #pragma unroll
    for (int k = 0; k < 16; ++k) {
        int j = (k << 1) | half;
        if (s_ids[side][j] == myid) loA |= (1u << (2 * k));
        if (s_ids[os][j]   == myid) loX |= (1u << (2 * k));
    }
    #pragma unroll
    for (int k = 16; k < 32; ++k) {
        int j = (k << 1) | half;
        if (s_ids[side][j] == myid) hiA |= (1u << (2 * k - 32));
        if (s_ids[os][j]   == myid) hiX |= (1u << (2 * k - 32));
    }
    unsigned long long m_own =
        (((unsigned long long)hiA << 32) | loA) << half;
    unsigned long long m_oth =
        (((unsigned long long)hiX << 32) | loX) << half;
    m_own |= __shfl_xor_sync(0xFFFFFFFFu, m_own, 1);
    m_oth |= __shfl_xor_sync(0xFFFFFFFFu, m_oth, 1);

    const int n     = __popcll(m_own);
    const int split = n >> 1;

    // ---- sparse group stats: half0 -> extrema, half1 -> t_split ----
    float tmax = -3.402823466e38f, tmin = 3.402823466e38f, ts = 0.f;
    if (!half) {
        unsigned long long m = m_own;
        while (m) {
            int j = __ffsll((long long)m) - 1;
            m &= m - 1;
            float tj = s_t[side][j];
            tmax = fmaxf(tmax, tj);
            tmin = fminf(tmin, tj);
        }
    } else if (n >= 4) {
        unsigned long long mc = m_own;
        while (mc) {
            int j = __ffsll((long long)mc) - 1;
            mc &= mc - 1;
            float tj = s_t[side][j];
            int r = 0;
            unsigned long long mi = m_own;
            while (mi) {
                int q = __ffsll((long long)mi) - 1;
                mi &= mi - 1;
                float tq = s_t[side][q];
                r += (tq < tj) || (tq == tj && q < j);
            }
            if (r == split) ts = tj;
        }
    }
    ts = __shfl_xor_sync(0xFFFFFFFFu, ts, 1) + ts;  // half0 gets half1's ts (its own is 0)

    if (!half) {
        float nf  = (float)n;
        float avg = (n > 1) ? (tmax - tmin) / (nf - 1.f) : 0.f;
        float den = fmaxf(nf - (float)split - 1.f, 1.f);
        float rec = (n >= 4) ? (tmax - ts) / den : 0.f;
        if (myid == 0) { avg = 0.f; rec = 0.f; }
        s_avg[side][i] = avg;
        s_rec[side][i] = rec;
    }
    __syncthreads();

    // ---- features: O(1) cross lookups ----
    if (!half) {
        float cur_t      = itimes[b];
        int   other_node = side ? src_nid[b] : dst_nid[b];

        int co = __popcll(m_oth);
        float lt = 0.f, iat_o = 0.f, riat_o = 0.f;
        if (m_oth) {
            int jf = __ffsll((long long)m_oth) - 1;
            int jl = 63 - __clzll((long long)m_oth);
            lt     = s_t[os][jl];
            iat_o  = s_avg[os][jf];
            riat_o = s_rec[os][jf];
        }
        float my_avg = s_avg[side][i], my_rec = s_rec[side][i];

        float f0 = (float)n;
        float f1 = (float)co;
        float f2 = (myid == other_node) ? 1.f : 0.f;
        float f3 = (co > 0) ? 1.f : 0.f;
        float f4 = (co > 0) ? f0 / (f1 + EPSQ) : 0.f;
        float rcy_self  = cur_t - myt;
        float rcy_other = cur_t - lt;
        float f5 = (rcy_self > EPSQ) ? rcy_other / (rcy_self + EPSQ) : 0.f;
        float f6 = (iat_o  > EPSQ) ? my_avg / (iat_o  + EPSQ) : 0.f;
        float f7 = (riat_o > EPSQ) ? my_rec / (riat_o + EPSQ) : 0.f;
        if (myid == 0) { f0 = f1 = f2 = f3 = f4 = f5 = f6 = f7 = 0.f; }

        float sp = fmaxf(f0,0.f)+fmaxf(f1,0.f)+fmaxf(f2,0.f)+fmaxf(f3,0.f)
                 + fmaxf(f4,0.f)+fmaxf(f5,0.f)+fmaxf(f6,0.f)+fmaxf(f7,0.f);
        float sn = fminf(f0,0.f)+fminf(f1,0.f)+fminf(f2,0.f)+fminf(f3,0.f)
                 + fminf(f4,0.f)+fminf(f5,0.f)+fminf(f6,0.f)+fminf(f7,0.f);
        s_Sp[side][i] = sp;
        s_Sn[side][i] = sn;

        if (!fast) {
            float* fp = &s_feat[side][i][0];
            fp[0]=f0; fp[1]=f1; fp[2]=f2; fp[3]=f3;
            fp[4]=f4; fp[5]=f5; fp[6]=f6; fp[7]=f7;
        }
    }
    __syncthreads();

    if (fast) {
        // ---- fast path: y = Sp*Vp + Sn*Vn + Vb, float4 streamed ----
        const int e4 = tid & 31;
        float4 vp = ((const float4*)s_Vp)[e4];
        float4 vn = ((const float4*)s_Vn)[e4];
        float4 bb = ((const float4*)s_Vb)[e4];

        const size_t sideStride = (size_t)B * (LQ * DQ);
        float* base0 = out + (size_t)b * (LQ * DQ);
        #pragma unroll
        for (int k = 0; k < 16; ++k) {
            int w    = tid + k * 256;
            int l    = (w >> 5) & 63;
            int sd   = w >> 11;
            float sp = s_Sp[sd][l], sn = s_Sn[sd][l];
            float4 y;
            y.x = fmaf(sp, vp.x, fmaf(sn, vn.x, bb.x));
            y.y = fmaf(sp, vp.y, fmaf(sn, vn.y, bb.y));
            y.z = fmaf(sp, vp.z, fmaf(sn, vn.z, bb.z));
            y.w = fmaf(sp, vp.w, fmaf(sn, vn.w, bb.w));
            float4* row = (float4*)(base0 + (size_t)sd * sideStride + (size_t)l * DQ);
            __stcs(&row[e4], y);
        }
    } else {
        // ---- general-b1 path (never taken with this dataset's b1 == 0) ----
        __shared__ float sW1[DQ], sb1[DQ];
        if (tid < DQ) { sW1[tid] = W1[tid]; sb1[tid] = b1[tid]; }
        __syncthreads();
        const size_t sideStride = (size_t)B * (LQ * DQ);
        for (int w = tid; w < 2 * LQ * DQ; w += 256) {
            int e    = w & 127;
            int row  = w >> 7;
            int sd   = row >> 6, l = row & 63;
            float y = 8.f * __ldg(&b2[e]);
            #pragma unroll
            for (int f = 0; f < 8; ++f) {
                float fv  = s_feat[sd][l][f];
                float acc = 0.f;
                for (int d = 0; d < DQ; ++d) {
                    float h = fmaxf(fmaf(fv, sW1[d], sb1[d]), 0.f);
                    acc = fmaf(h, __ldg(&W2[d * DQ + e]), acc);
                }
                y += acc;
            }
            out[(size_t)sd * sideStride + (size_t)b * (LQ * DQ) + (size_t)l * DQ + e] = y;
        }
    }
}

// ---------------------------------------------------------------------------
extern "C" void kernel_launch(void* const* d_in, const int* in_sizes, int n_in,
                              void* d_out, int out_size) {
    const int*   src_ids = (const int*)  d_in[0];
    const int*   dst_ids = (const int*)  d_in[1];
    const int*   src_nid = (const int*)  d_in[2];
    const int*   dst_nid = (const int*)  d_in[3];
    const float* itimes  = (const float*)d_in[4];
    const float* src_t   = (const float*)d_in[5];
    const float* dst_t   = (const float*)d_in[6];
    const float* W1      = (const float*)d_in[7];
    const float* b1      = (const float*)d_in[8];
    const float* W2      = (const float*)d_in[9];
    const float* b2      = (const float*)d_in[10];
    float* out = (float*)d_out;
    int B = in_sizes[2];  // src_node_ids count

    prep_kernel<<<1, 1024>>>(W1, b1, W2, b2);
    lpe_main_kernel<<<B, 256>>>(src_ids, dst_ids, src_nid, dst_nid,
                                itimes, src_t, dst_t,
                                W1, b1, W2, b2, out, B);
}